// round 14
// baseline (speedup 1.0000x reference)
#include <cuda_runtime.h>
#include <cuda_bf16.h>
#include <cuda_fp16.h>
#include <math.h>
#include <stdint.h>

#define N_ 2048
#define D_ 512
#define K_ 65536

constexpr float TEMP_INV = 5.0f;
constexpr float CSHIFT   = 5.0f;
constexpr float EPS      = 1e-8f;
constexpr float QNT      = 400.0f;                 // int8 quant scale for q-hat / u-hat
constexpr float INV_SCALE = TEMP_INV / (QNT * QNT);   // acc -> logit (3.125e-5)

// ---------------- device scratch (allocation-free rule) ----------------
__device__ float g_lpos[N_];
__device__ float g_S[N_];
__device__ unsigned g_cnt;
__device__ uint32_t g_Q8[N_ * D_ / 4];   // 1 MB  s8(400 * q/||q||)
__device__ uint32_t g_U8[K_ * D_ / 4];   // 32 MB s8(400 * u/||u||)

// ---------------- PTX helpers ----------------
__device__ __forceinline__ uint32_t smem_u32(const void* p) {
    uint32_t a;
    asm("{ .reg .u64 t; cvta.to.shared.u64 t, %1; cvt.u32.u64 %0, t; }" : "=r"(a) : "l"(p));
    return a;
}

#define CP_ASYNC16(dst, src) \
    asm volatile("cp.async.cg.shared.global [%0], [%1], 16;\n" :: "r"(dst), "l"(src))
#define CP_COMMIT() asm volatile("cp.async.commit_group;\n" ::: "memory")
#define CP_WAIT(n)  asm volatile("cp.async.wait_group %0;\n" :: "n"(n) : "memory")

#define LDSM4(R0, R1, R2, R3, addr) \
    asm volatile("ldmatrix.sync.aligned.m8n8.x4.shared.b16 {%0,%1,%2,%3}, [%4];" \
        : "=r"(R0), "=r"(R1), "=r"(R2), "=r"(R3) : "r"(addr))

// int8 MMA, int32 accumulate; fragment layout byte-identical to e4m3 k32.
#define MMAS8(D, A, B0, B1) \
    asm volatile("mma.sync.aligned.m16n8k32.row.col.s32.s8.s8.s32 " \
        "{%0,%1,%2,%3}, {%4,%5,%6,%7}, {%8,%9}, {%0,%1,%2,%3};" \
        : "+r"((D)[0]), "+r"((D)[1]), "+r"((D)[2]), "+r"((D)[3]) \
        : "r"((A)[0]), "r"((A)[1]), "r"((A)[2]), "r"((A)[3]), "r"(B0), "r"(B1))

__device__ __forceinline__ float warp_sum(float v) {
#pragma unroll
    for (int o = 16; o > 0; o >>= 1) v += __shfl_xor_sync(0xffffffffu, v, o);
    return v;
}

__device__ __forceinline__ int q8(float x) {
    return __float2int_rn(fmaxf(-127.0f, fminf(127.0f, x)));
}
__device__ __forceinline__ uint32_t pack_s8x4(float e0, float e1, float e2, float e3) {
    uint32_t v0 = (uint32_t)q8(e0) & 0xffu,  v1 = (uint32_t)q8(e1) & 0xffu;
    uint32_t v2 = (uint32_t)q8(e2) & 0xffu,  v3 = (uint32_t)q8(e3) & 0xffu;
    return v0 | (v1 << 8) | (v2 << 16) | (v3 << 24);
}

// ---------------------------------------------------------------------------
// Merged prep: blocks [0,N_) = query/keys; blocks [N_, N_+K_) = queue.
// ---------------------------------------------------------------------------
__global__ void prep(const float* __restrict__ q, const float* __restrict__ k,
                     const float* __restrict__ u) {
    int tid = threadIdx.x;  // 128
    int wid = tid >> 5, lid = tid & 31;

    if ((int)blockIdx.x < N_) {
        int n = blockIdx.x;
        if (n == 0 && tid == 0) g_cnt = 0;
        float4 a = ((const float4*)(q + (size_t)n * D_))[tid];
        float4 b = ((const float4*)(k + (size_t)n * D_))[tid];
        float sq = a.x * a.x + a.y * a.y + a.z * a.z + a.w * a.w;
        float sk = b.x * b.x + b.y * b.y + b.z * b.z + b.w * b.w;
        float dp = a.x * b.x + a.y * b.y + a.z * b.z + a.w * b.w;

        __shared__ float s_sq[4], s_sk[4], s_dp[4];
        __shared__ float s_scale;
        sq = warp_sum(sq); sk = warp_sum(sk); dp = warp_sum(dp);
        if (lid == 0) { s_sq[wid] = sq; s_sk[wid] = sk; s_dp[wid] = dp; }
        __syncthreads();
        if (tid == 0) {
            float tsq = s_sq[0] + s_sq[1] + s_sq[2] + s_sq[3];
            float tsk = s_sk[0] + s_sk[1] + s_sk[2] + s_sk[3];
            float tdp = s_dp[0] + s_dp[1] + s_dp[2] + s_dp[3];
            float qn = sqrtf(tsq), kn = sqrtf(tsk);
            float lpos = tdp / fmaxf(qn * kn, EPS) * TEMP_INV;
            g_lpos[n] = lpos;
            g_S[n] = expf(lpos - CSHIFT);
            s_scale = QNT / qn;
        }
        __syncthreads();
        float s = s_scale;
        g_Q8[(size_t)n * 128 + tid] = pack_s8x4(a.x * s, a.y * s, a.z * s, a.w * s);
    } else {
        int r = blockIdx.x - N_;
        float4 a = ((const float4*)(u + (size_t)r * D_))[tid];
        float s = a.x * a.x + a.y * a.y + a.z * a.z + a.w * a.w;
        __shared__ float sm[4];
        __shared__ float s_scale;
        s = warp_sum(s);
        if (lid == 0) sm[wid] = s;
        __syncthreads();
        if (tid == 0) s_scale = QNT * rsqrtf(sm[0] + sm[1] + sm[2] + sm[3]);
        __syncthreads();
        float sc = s_scale;
        g_U8[(size_t)r * 128 + tid] = pack_s8x4(a.x * sc, a.y * sc, a.z * sc, a.w * sc);
    }
}

// ---------------------------------------------------------------------------
// GEMM+LSE via int8 mma.m16n8k32 (s8 -> s32 acc).
// CTA 128(M,queue) x 128(N,query), BK=64, 3-stage cp.async, warps 2Mx4N,
// warp tile 64x32 (s32 acc = 64 regs).  2 CTAs/SM, static unroll.
// ---------------------------------------------------------------------------
constexpr int BM = 128, BN = 128, BK = 64;
constexpr uint32_t ROWB = 80;
constexpr uint32_t A_BYTES = 128 * ROWB;           // 10240
constexpr uint32_t STAGE_BYTES = 2 * A_BYTES;      // 20480
constexpr int NSTAGE = 3;
constexpr uint32_t SMEM_TOTAL = NSTAGE * STAGE_BYTES;  // 61440
constexpr int NIT = D_ / BK;                       // 8
constexpr int TOTAL_CTAS = (N_ / BN) * (K_ / BM);  // 8192
constexpr uint32_t ROW64_SMEM = 64 * ROWB;
constexpr int ROW64_GMEM = 64 * D_;

__global__ __launch_bounds__(256, 2) void gemm_lse_s8(float* __restrict__ out) {
    extern __shared__ __align__(128) char smem[];
    const uint32_t sb = smem_u32(smem);
    const int tid = threadIdx.x;
    const int wid = tid >> 5, lane = tid & 31;
    const int n0 = blockIdx.x * BN;      // query tile (fast -> U8 shared via L2)
    const int m0 = blockIdx.y * BM;      // queue tile
    const int warp_m = wid & 1;          // 0..1 -> 64 rows
    const int warp_n = wid >> 1;         // 0..3 -> 32 cols

    // ---- cp.async addressing: 2 base pointers + fixed +64-row deltas ----
    const int lrow = tid >> 2, lcol = (tid & 3) * 16;
    const uint8_t* srcA = (const uint8_t*)g_U8 + (size_t)(m0 + lrow) * D_ + lcol;
    const uint8_t* srcB = (const uint8_t*)g_Q8 + (size_t)(n0 + lrow) * D_ + lcol;
    const uint32_t dA = lrow * ROWB + lcol;
    const uint32_t dB = A_BYTES + dA;

    int acc[4][4][4];                    // s32 accumulators, 64 regs
#pragma unroll
    for (int i = 0; i < 4; i++)
#pragma unroll
        for (int j = 0; j < 4; j++)
#pragma unroll
            for (int r = 0; r < 4; r++) acc[i][j][r] = 0;

    // ---- prologue: fill 2 stages ----
#pragma unroll
    for (int s = 0; s < 2; s++) {
        uint32_t base = sb + s * STAGE_BYTES;
        CP_ASYNC16(base + dA, srcA);
        CP_ASYNC16(base + dA + ROW64_SMEM, srcA + ROW64_GMEM);
        CP_ASYNC16(base + dB, srcB);
        CP_ASYNC16(base + dB + ROW64_SMEM, srcB + ROW64_GMEM);
        CP_COMMIT();
        srcA += BK; srcB += BK;
    }

    const uint32_t aOff = (warp_m * 64 + (lane & 15)) * ROWB + ((lane >> 4) * 16);
    const uint32_t bOff = A_BYTES + (warp_n * 32 + (lane & 15)) * ROWB + ((lane >> 4) * 16);

#pragma unroll
    for (int it = 0; it < NIT; it++) {
        if (it < NIT - 1) { CP_WAIT(1); } else { CP_WAIT(0); }
        __syncthreads();
        if (it + 2 < NIT) {
            uint32_t base = sb + ((it + 2) % 3) * STAGE_BYTES;
            CP_ASYNC16(base + dA, srcA);
            CP_ASYNC16(base + dA + ROW64_SMEM, srcA + ROW64_GMEM);
            CP_ASYNC16(base + dB, srcB);
            CP_ASYNC16(base + dB + ROW64_SMEM, srcB + ROW64_GMEM);
            CP_COMMIT();
            srcA += BK; srcB += BK;
        }
        const uint32_t stb = sb + (it % 3) * STAGE_BYTES;
#pragma unroll
        for (int ks = 0; ks < 2; ks++) {      // two k32 steps per BK=64
            uint32_t a[4][4], b[2][4];
            LDSM4(a[0][0], a[0][1], a[0][2], a[0][3],
                  stb + aOff + ks * 32);
#pragma unroll
            for (int ng = 0; ng < 2; ng++)
                LDSM4(b[ng][0], b[ng][1], b[ng][2], b[ng][3],
                      stb + bOff + ng * 16 * ROWB + ks * 32);
#pragma unroll
            for (int mt = 1; mt < 4; mt++)
                LDSM4(a[mt][0], a[mt][1], a[mt][2], a[mt][3],
                      stb + aOff + mt * 16 * ROWB + ks * 32);
#pragma unroll
            for (int mt = 0; mt < 4; mt++) {
#pragma unroll
                for (int ng = 0; ng < 2; ng++) {
                    MMAS8(acc[mt][2 * ng + 0], a[mt], b[ng][0], b[ng][2]);
                    MMAS8(acc[mt][2 * ng + 1], a[mt], b[ng][1], b[ng][3]);
                }
            }
        }
    }

    // Epilogue: logit = acc * INV_SCALE; exp(l-5); reduce over 64 warp rows.
#pragma unroll
    for (int j = 0; j < 4; j++) {
        float s0 = 0.0f, s1 = 0.0f;
#pragma unroll
        for (int mt = 0; mt < 4; mt++) {
            s0 += __expf(fmaf((float)acc[mt][j][0], INV_SCALE, -CSHIFT))
                + __expf(fmaf((float)acc[mt][j][2], INV_SCALE, -CSHIFT));
            s1 += __expf(fmaf((float)acc[mt][j][1], INV_SCALE, -CSHIFT))
                + __expf(fmaf((float)acc[mt][j][3], INV_SCALE, -CSHIFT));
        }
#pragma unroll
        for (int o = 4; o <= 16; o <<= 1) {
            s0 += __shfl_xor_sync(0xffffffffu, s0, o);
            s1 += __shfl_xor_sync(0xffffffffu, s1, o);
        }
        if (lane < 4) {
            int col = n0 + warp_n * 32 + j * 8 + lane * 2;
            atomicAdd(&g_S[col], s0);
            atomicAdd(&g_S[col + 1], s1);
        }
    }

    // Fused finalize: last CTA computes the loss.
    __shared__ bool s_last;
    __threadfence();
    __syncthreads();
    if (tid == 0) s_last = (atomicAdd(&g_cnt, 1u) == TOTAL_CTAS - 1);
    __syncthreads();
    if (s_last) {
        float local = 0.0f;
        for (int n = tid; n < N_; n += 256)
            local += CSHIFT + logf(__ldcg(&g_S[n])) - g_lpos[n];
        __shared__ float red[256];
        red[tid] = local;
        __syncthreads();
        for (int s = 128; s > 0; s >>= 1) {
            if (tid < s) red[tid] += red[tid + s];
            __syncthreads();
        }
        if (tid == 0) out[0] = red[0] / (float)N_;
    }
}

extern "C" void kernel_launch(void* const* d_in, const int* in_sizes, int n_in,
                              void* d_out, int out_size) {
    const float* query = (const float*)d_in[0];
    const float* keys  = (const float*)d_in[1];
    const float* queue = (const float*)d_in[2];
    float* out = (float*)d_out;

    cudaFuncSetAttribute(gemm_lse_s8, cudaFuncAttributeMaxDynamicSharedMemorySize, SMEM_TOTAL);

    prep<<<N_ + K_, 128>>>(query, keys, queue);
    dim3 grid(N_ / BN, K_ / BM);   // 16 x 512, x fast -> U8 tiles shared in L2
    gemm_lse_s8<<<grid, 256, SMEM_TOTAL>>>(out);
}

// round 15
// speedup vs baseline: 2.5724x; 2.5724x over previous
#include <cuda_runtime.h>
#include <cuda_bf16.h>
#include <cuda_fp16.h>
#include <math.h>
#include <stdint.h>

#define N_ 2048
#define D_ 512
#define K_ 65536

constexpr float TEMP_INV = 5.0f;
constexpr float CSHIFT   = 5.0f;
constexpr float EPS      = 1e-8f;
constexpr float QSCALE   = 16.0f;
constexpr float USCALE   = 16.0f;

// ---------------- device scratch (allocation-free rule) ----------------
__device__ float g_lpos[N_];
__device__ float g_S[N_];
__device__ unsigned g_cnt;
__device__ uint32_t g_Q8[N_ * D_ / 4];   // 1 MB  e4m3(80 * q/||q||)
__device__ uint32_t g_U8[K_ * D_ / 4];   // 32 MB e4m3(16 * u/||u||)

// ---------------- PTX helpers ----------------
__device__ __forceinline__ uint32_t smem_u32(const void* p) {
    uint32_t a;
    asm("{ .reg .u64 t; cvta.to.shared.u64 t, %1; cvt.u32.u64 %0, t; }" : "=r"(a) : "l"(p));
    return a;
}

#define CP_ASYNC16(dst, src) \
    asm volatile("cp.async.cg.shared.global [%0], [%1], 16;\n" :: "r"(dst), "l"(src))
#define CP_COMMIT() asm volatile("cp.async.commit_group;\n" ::: "memory")
#define CP_WAIT(n)  asm volatile("cp.async.wait_group %0;\n" :: "n"(n) : "memory")

#define LDSM4(R0, R1, R2, R3, addr) \
    asm volatile("ldmatrix.sync.aligned.m8n8.x4.shared.b16 {%0,%1,%2,%3}, [%4];" \
        : "=r"(R0), "=r"(R1), "=r"(R2), "=r"(R3) : "r"(addr))

// fp8 e4m3 MMA, fp16 accumulate (2 regs)
#define MMAFP8H(D, A, B0, B1) \
    asm volatile("mma.sync.aligned.m16n8k32.row.col.f16.e4m3.e4m3.f16 " \
        "{%0,%1}, {%2,%3,%4,%5}, {%6,%7}, {%0,%1};" \
        : "+r"((D)[0]), "+r"((D)[1]) \
        : "r"((A)[0]), "r"((A)[1]), "r"((A)[2]), "r"((A)[3]), "r"(B0), "r"(B1))

#define EX2_F16X2(d, s) \
    asm("ex2.approx.f16x2 %0, %1;" : "=r"(d) : "r"(s))

__device__ __forceinline__ float warp_sum(float v) {
#pragma unroll
    for (int o = 16; o > 0; o >>= 1) v += __shfl_xor_sync(0xffffffffu, v, o);
    return v;
}

__device__ __forceinline__ uint32_t pack_e4m3x4(float e0, float e1, float e2, float e3) {
    uint16_t lo, hi;
    asm("cvt.rn.satfinite.e4m3x2.f32 %0, %1, %2;" : "=h"(lo) : "f"(e1), "f"(e0));
    asm("cvt.rn.satfinite.e4m3x2.f32 %0, %1, %2;" : "=h"(hi) : "f"(e3), "f"(e2));
    return (uint32_t)lo | ((uint32_t)hi << 16);
}

// ---------------------------------------------------------------------------
// Barrier-free prep: one WARP per row (8 rows/block, 256 threads).
// Rows [0,N_) = query/keys path; rows [N_, N_+K_) = queue path.
// Lane l handles float4 chunks l, l+32, l+64, l+96 of the 128-chunk row.
// ---------------------------------------------------------------------------
constexpr int PREP_ROWS = N_ + K_;                 // 67584
constexpr int PREP_BLOCKS = PREP_ROWS / 8;

__global__ __launch_bounds__(256) void prep(const float* __restrict__ q,
                                            const float* __restrict__ k,
                                            const float* __restrict__ u) {
    const int wid = threadIdx.x >> 5, lane = threadIdx.x & 31;
    const int row = blockIdx.x * 8 + wid;
    if (row == 0 && lane == 0) g_cnt = 0;

    if (row < N_) {
        const int n = row;
        const float4* q4 = (const float4*)(q + (size_t)n * D_);
        const float4* k4 = (const float4*)(k + (size_t)n * D_);
        float4 av[4], bv[4];
        float sq = 0.0f, sk = 0.0f, dp = 0.0f;
#pragma unroll
        for (int i = 0; i < 4; i++) {
            av[i] = q4[lane + i * 32];
            bv[i] = k4[lane + i * 32];
            sq += av[i].x * av[i].x + av[i].y * av[i].y + av[i].z * av[i].z + av[i].w * av[i].w;
            sk += bv[i].x * bv[i].x + bv[i].y * bv[i].y + bv[i].z * bv[i].z + bv[i].w * bv[i].w;
            dp += av[i].x * bv[i].x + av[i].y * bv[i].y + av[i].z * bv[i].z + av[i].w * bv[i].w;
        }
        sq = warp_sum(sq); sk = warp_sum(sk); dp = warp_sum(dp);
        float qn = sqrtf(sq), kn = sqrtf(sk);
        if (lane == 0) {
            float lpos = dp / fmaxf(qn * kn, EPS) * TEMP_INV;
            g_lpos[n] = lpos;
            g_S[n] = expf(lpos - CSHIFT);
        }
        float s = TEMP_INV * QSCALE / qn;
        uint32_t* dst = g_Q8 + (size_t)n * 128;
#pragma unroll
        for (int i = 0; i < 4; i++)
            dst[lane + i * 32] = pack_e4m3x4(av[i].x * s, av[i].y * s, av[i].z * s, av[i].w * s);
    } else {
        const int r = row - N_;
        const float4* u4 = (const float4*)(u + (size_t)r * D_);
        float4 av[4];
        float ss = 0.0f;
#pragma unroll
        for (int i = 0; i < 4; i++) {
            av[i] = u4[lane + i * 32];
            ss += av[i].x * av[i].x + av[i].y * av[i].y + av[i].z * av[i].z + av[i].w * av[i].w;
        }
        ss = warp_sum(ss);
        float s = USCALE * rsqrtf(ss);
        uint32_t* dst = g_U8 + (size_t)r * 128;
#pragma unroll
        for (int i = 0; i < 4; i++)
            dst[lane + i * 32] = pack_e4m3x4(av[i].x * s, av[i].y * s, av[i].z * s, av[i].w * s);
    }
}

// ---------------------------------------------------------------------------
// GEMM+LSE via fp8 mma.m16n8k32 (e4m3 -> f16 acc).
// CTA 256(M,queue) x 128(N,query), BK=64, warps 4Mx2N, warp tile 64x64.
// 3-stage cp.async, 2 CTAs/SM, static unroll.  Inner loop interleaved:
// MMA(mt=0) issued before a1-3 LDSM so their latency hides under compute.
// Epilogue in packed f16 (hfma2 -> ex2.f16x2 -> hadd2 -> packed shfl).
// ---------------------------------------------------------------------------
constexpr int BM = 256, BN = 128, BK = 64;
constexpr uint32_t ROWB = 80;
constexpr uint32_t A_BYTES = 256 * ROWB;           // 20480
constexpr uint32_t B_BYTES = 128 * ROWB;           // 10240
constexpr uint32_t STAGE_BYTES = A_BYTES + B_BYTES;    // 30720
constexpr int NSTAGE = 3;
constexpr uint32_t SMEM_TOTAL = NSTAGE * STAGE_BYTES;  // 92160
constexpr int NIT = D_ / BK;                       // 8
constexpr int TOTAL_CTAS = (N_ / BN) * (K_ / BM);  // 4096
constexpr uint32_t ROW64_SMEM = 64 * ROWB;
constexpr int ROW64_GMEM = 64 * D_;

__global__ __launch_bounds__(256, 2) void gemm_lse_fp8(float* __restrict__ out) {
    extern __shared__ __align__(128) char smem[];
    const uint32_t sb = smem_u32(smem);
    const int tid = threadIdx.x;
    const int wid = tid >> 5, lane = tid & 31;
    const int n0 = blockIdx.x * BN;      // query tile (fast -> U8 shared via L2)
    const int m0 = blockIdx.y * BM;      // queue tile
    const int warp_m = wid & 3;          // 0..3 -> 64 rows each
    const int warp_n = wid >> 2;         // 0..1 -> 64 cols each

    // ---- cp.async addressing: 2 base pointers, fixed +64-row deltas ----
    const int lrow = tid >> 2, lcol = (tid & 3) * 16;   // lrow 0..63
    const uint8_t* srcA = (const uint8_t*)g_U8 + (size_t)(m0 + lrow) * D_ + lcol;
    const uint8_t* srcB = (const uint8_t*)g_Q8 + (size_t)(n0 + lrow) * D_ + lcol;
    const uint32_t dA = lrow * ROWB + lcol;
    const uint32_t dB = A_BYTES + dA;

    uint32_t acc[4][8][2];               // f16x2 accumulators, 64 regs
#pragma unroll
    for (int i = 0; i < 4; i++)
#pragma unroll
        for (int j = 0; j < 8; j++) { acc[i][j][0] = 0u; acc[i][j][1] = 0u; }

    // ---- prologue: fill 2 stages ----
#pragma unroll
    for (int s = 0; s < 2; s++) {
        uint32_t base = sb + s * STAGE_BYTES;
#pragma unroll
        for (int r = 0; r < 4; r++)      // A: rows lrow + {0,64,128,192}
            CP_ASYNC16(base + dA + r * ROW64_SMEM, srcA + r * ROW64_GMEM);
#pragma unroll
        for (int r = 0; r < 2; r++)      // B: rows lrow + {0,64}
            CP_ASYNC16(base + dB + r * ROW64_SMEM, srcB + r * ROW64_GMEM);
        CP_COMMIT();
        srcA += BK; srcB += BK;
    }

    const uint32_t aOff = (warp_m * 64 + (lane & 15)) * ROWB + ((lane >> 4) * 16);
    const uint32_t bOff = A_BYTES + (warp_n * 64 + (lane & 15)) * ROWB + ((lane >> 4) * 16);

#pragma unroll
    for (int it = 0; it < NIT; it++) {
        if (it < NIT - 1) { CP_WAIT(1); } else { CP_WAIT(0); }
        __syncthreads();
        if (it + 2 < NIT) {
            uint32_t base = sb + ((it + 2) % 3) * STAGE_BYTES;
#pragma unroll
            for (int r = 0; r < 4; r++)
                CP_ASYNC16(base + dA + r * ROW64_SMEM, srcA + r * ROW64_GMEM);
#pragma unroll
            for (int r = 0; r < 2; r++)
                CP_ASYNC16(base + dB + r * ROW64_SMEM, srcB + r * ROW64_GMEM);
            CP_COMMIT();
            srcA += BK; srcB += BK;
        }
        const uint32_t stb = sb + (it % 3) * STAGE_BYTES;
#pragma unroll
        for (int ks = 0; ks < 2; ks++) {
            uint32_t a[4][4], b[4][4];
            // a0 + b fragments first...
            LDSM4(a[0][0], a[0][1], a[0][2], a[0][3],
                  stb + aOff + ks * 32);
#pragma unroll
            for (int ng = 0; ng < 4; ng++)
                LDSM4(b[ng][0], b[ng][1], b[ng][2], b[ng][3],
                      stb + bOff + ng * 16 * ROWB + ks * 32);
            // ...then MMA(mt=0) immediately, hiding a1-3 LDSM latency beneath it
#pragma unroll
            for (int ng = 0; ng < 4; ng++) {
                MMAFP8H(acc[0][2 * ng + 0], a[0], b[ng][0], b[ng][2]);
                MMAFP8H(acc[0][2 * ng + 1], a[0], b[ng][1], b[ng][3]);
            }
#pragma unroll
            for (int mt = 1; mt < 4; mt++)
                LDSM4(a[mt][0], a[mt][1], a[mt][2], a[mt][3],
                      stb + aOff + mt * 16 * ROWB + ks * 32);
#pragma unroll
            for (int mt = 1; mt < 4; mt++) {
#pragma unroll
                for (int ng = 0; ng < 4; ng++) {
                    MMAFP8H(acc[mt][2 * ng + 0], a[mt], b[ng][0], b[ng][2]);
                    MMAFP8H(acc[mt][2 * ng + 1], a[mt], b[ng][1], b[ng][3]);
                }
            }
        }
    }

    // Epilogue in packed f16: exp(acc/256 - 5) = 2^(acc*cmul + cadd)
    const __half2 cmul = __float2half2_rn(0.0056355275f);   // log2(e)/256
    const __half2 cadd = __float2half2_rn(-7.2134752f);     // -5*log2(e)
#pragma unroll
    for (int j = 0; j < 8; j++) {
        __half2 sum = __float2half2_rn(0.0f);
#pragma unroll
        for (int mt = 0; mt < 4; mt++) {
            __half2 t0 = __hfma2(*(const __half2*)&acc[mt][j][0], cmul, cadd);
            __half2 t1 = __hfma2(*(const __half2*)&acc[mt][j][1], cmul, cadd);
            uint32_t e0, e1;
            EX2_F16X2(e0, *(const uint32_t*)&t0);
            EX2_F16X2(e1, *(const uint32_t*)&t1);
            sum = __hadd2(sum, *(const __half2*)&e0);
            sum = __hadd2(sum, *(const __half2*)&e1);
        }
        uint32_t us = *(const uint32_t*)&sum;
#pragma unroll
        for (int o = 4; o <= 16; o <<= 1) {            // packed reduce over rows
            uint32_t ot = __shfl_xor_sync(0xffffffffu, us, o);
            __half2 hs = __hadd2(*(const __half2*)&us, *(const __half2*)&ot);
            us = *(const uint32_t*)&hs;
        }
        if (lane < 4) {
            float2 f = __half22float2(*(const __half2*)&us);
            int col = n0 + warp_n * 64 + j * 8 + lane * 2;
            atomicAdd(&g_S[col], f.x);
            atomicAdd(&g_S[col + 1], f.y);
        }
    }

    // Fused finalize: last CTA computes the loss.
    __shared__ bool s_last;
    __threadfence();
    __syncthreads();
    if (tid == 0) s_last = (atomicAdd(&g_cnt, 1u) == TOTAL_CTAS - 1);
    __syncthreads();
    if (s_last) {
        float local = 0.0f;
        for (int n = tid; n < N_; n += 256)
            local += CSHIFT + logf(__ldcg(&g_S[n])) - g_lpos[n];
        __shared__ float red[256];
        red[tid] = local;
        __syncthreads();
        for (int s = 128; s > 0; s >>= 1) {
            if (tid < s) red[tid] += red[tid + s];
            __syncthreads();
        }
        if (tid == 0) out[0] = red[0] / (float)N_;
    }
}

extern "C" void kernel_launch(void* const* d_in, const int* in_sizes, int n_in,
                              void* d_out, int out_size) {
    const float* query = (const float*)d_in[0];
    const float* keys  = (const float*)d_in[1];
    const float* queue = (const float*)d_in[2];
    float* out = (float*)d_out;

    cudaFuncSetAttribute(gemm_lse_fp8, cudaFuncAttributeMaxDynamicSharedMemorySize, SMEM_TOTAL);

    prep<<<PREP_BLOCKS, 256>>>(query, keys, queue);
    dim3 grid(N_ / BN, K_ / BM);   // 16 x 256, x fast -> U8 tiles shared in L2
    gemm_lse_fp8<<<grid, 256, SMEM_TOTAL>>>(out);
}